// round 14
// baseline (speedup 1.0000x reference)
#include <cuda_runtime.h>
#include <cuda_fp16.h>
#include <math.h>
#include <stdint.h>

#define NMAX   100000
#define C      64
#define KTAPS  343
#define TILE_M 128

// ---------------------------------------------------------------------------
// device scratch (no cudaMalloc allowed)
// ---------------------------------------------------------------------------
__device__ __align__(16) __half2 g_xh[(size_t)(NMAX + 1) * 32]; // x_feat fp16 [N+1][64], row N = zeros
__device__ __align__(16) __half2 g_w1h[KTAPS * 32];             // W1 fp16 [343][64]
__device__ __align__(16) __half  g_hh[(size_t)NMAX * 64];       // h post-GN fp16 [N][64]
__device__ __align__(16) uint4   g_w2f[2048];                   // W2^T fragments, lane-major
__device__ __align__(16) uint4   g_w3f[2048];                   // W3^T fragments, lane-major

__device__ __forceinline__ uint32_t pack_f16x2(float lo, float hi) {
    uint32_t u;
    asm("cvt.rn.f16x2.f32 %0, %1, %2;" : "=r"(u) : "f"(hi), "f"(lo));
    return u;
}

// tanh-form GELU with single-MUFU tanh.approx
__device__ __forceinline__ float gelu_fast(float x) {
    float x2 = x * x;
    float u  = fmaf(0.035677408136f, x2, 0.7978845608028654f);
    float ta = x * u;
    float t;
    asm("tanh.approx.f32 %0, %1;" : "=f"(t) : "f"(ta));
    float hx = 0.5f * x;
    return fmaf(hx, t, hx);
}

// D += A * B   (m16n8k16, f16 inputs, f32 accum; A row frag, B col frag)
#define MMA_F16(d, a, b0, b1)                                                           \
    asm volatile("mma.sync.aligned.m16n8k16.row.col.f32.f16.f16.f32 "                   \
                 "{%0,%1,%2,%3}, {%4,%5,%6,%7}, {%8,%9}, {%0,%1,%2,%3};"                \
                 : "+f"((d)[0]), "+f"((d)[1]), "+f"((d)[2]), "+f"((d)[3])               \
                 : "r"((a)[0]), "r"((a)[1]), "r"((a)[2]), "r"((a)[3]),                  \
                   "r"(b0), "r"(b1))

// ---------------------------------------------------------------------------
// Kernel 0: fp16 conversions + lane-major fragment-ordered weight images
// ---------------------------------------------------------------------------
__global__ void prep_kernel(const float* __restrict__ x,
                            const float* __restrict__ W1,
                            const float* __restrict__ W2,
                            const float* __restrict__ W3, int N) {
    int e = blockIdx.x * blockDim.x + threadIdx.x;
    int nx = (N + 1) * 8;                       // uint4 outputs for x (+ sentinel row)
    if (e < nx) {
        uint4 v = make_uint4(0, 0, 0, 0);
        if ((e >> 3) < N) {
            const float4* s = (const float4*)x + (size_t)e * 2;
            float4 a = s[0], b = s[1];
            v.x = pack_f16x2(a.x, a.y); v.y = pack_f16x2(a.z, a.w);
            v.z = pack_f16x2(b.x, b.y); v.w = pack_f16x2(b.z, b.w);
        }
        ((uint4*)g_xh)[e] = v;
        return;
    }
    int e1 = e - nx;
    if (e1 < KTAPS * 8) {
        const float4* s = (const float4*)W1 + (size_t)e1 * 2;
        float4 a = s[0], b = s[1];
        uint4 v;
        v.x = pack_f16x2(a.x, a.y); v.y = pack_f16x2(a.z, a.w);
        v.z = pack_f16x2(b.x, b.y); v.w = pack_f16x2(b.z, b.w);
        ((uint4*)g_w1h)[e1] = v;
        return;
    }
    int e2 = e1 - KTAPS * 8;
    if (e2 < 2048) {
        // lane-major W2 fragments: idx = (ch*8+nt)*64 + half*32 + lane
        int blk = e2 >> 6, half = (e2 >> 5) & 1, lane = e2 & 31;
        int ch = blk >> 3, nt = blk & 7;
        int g = lane >> 2, q = lane & 3;
        int n  = ch * 64 + nt * 8 + g;          // W2^T row (output unit)
        int kb = 32 * half + 2 * q;
        uint4 v;
        v.x = pack_f16x2(W2[(kb +  0) * 256 + n], W2[(kb +  1) * 256 + n]);
        v.y = pack_f16x2(W2[(kb +  8) * 256 + n], W2[(kb +  9) * 256 + n]);
        v.z = pack_f16x2(W2[(kb + 16) * 256 + n], W2[(kb + 17) * 256 + n]);
        v.w = pack_f16x2(W2[(kb + 24) * 256 + n], W2[(kb + 25) * 256 + n]);
        g_w2f[e2] = v;
        return;
    }
    int e3 = e2 - 2048;
    if (e3 < 2048) {
        // lane-major W3 fragments: idx = (ch*8+nt2)*64 + half*32 + lane
        int blk = e3 >> 6, half = (e3 >> 5) & 1, lane = e3 & 31;
        int ch = blk >> 3, nt2 = blk & 7;
        int g = lane >> 2, q = lane & 3;
        int c  = nt2 * 8 + g;                   // W3^T row (output channel)
        int jb = 32 * (2 * ch + half) + 2 * q;
        uint4 v;
        v.x = pack_f16x2(W3[(jb +  0) * 64 + c], W3[(jb +  1) * 64 + c]);
        v.y = pack_f16x2(W3[(jb +  8) * 64 + c], W3[(jb +  9) * 64 + c]);
        v.z = pack_f16x2(W3[(jb + 16) * 64 + c], W3[(jb + 17) * 64 + c]);
        v.w = pack_f16x2(W3[(jb + 24) * 64 + c], W3[(jb + 25) * 64 + c]);
        g_w3f[e3] = v;
    }
}

// ---------------------------------------------------------------------------
// Kernel 1: depthwise submanifold conv + bias + GroupNorm
// one warp per voxel; compacted tap list; 16 taps/iter -> 8 LDG.128 in flight
// ---------------------------------------------------------------------------
#define DW_WARPS 8

__device__ __forceinline__ void accum8(float* acc, uint4 f, uint4 w) {
    const __half2* fh = (const __half2*)&f;
    const __half2* wh = (const __half2*)&w;
    #pragma unroll
    for (int m = 0; m < 4; ++m) {
        float2 p = __half22float2(__hmul2(fh[m], wh[m]));
        acc[2 * m]     += p.x;
        acc[2 * m + 1] += p.y;
    }
}

__global__ __launch_bounds__(256)
void dwconv_gn_kernel(const int*   __restrict__ nbr,
                      const float* __restrict__ b1,
                      const float* __restrict__ gamma,
                      const float* __restrict__ beta,
                      int N) {
    __shared__ int s_list[DW_WARPS][352];

    const int wslot = threadIdx.x >> 5;
    const int lane  = threadIdx.x & 31;
    const int grp   = lane >> 3;     // tap slot 0..3
    const int sub   = lane & 7;      // channel slice (8 ch)
    const int i = blockIdx.x * DW_WARPS + wslot;
    if (i >= N) return;

    const int* row = nbr + (long long)i * KTAPS;
    int* list = s_list[wslot];

    // ---- phase 1: compact valid (src, tap) into smem list ----
    int cnt = 0;
    #pragma unroll
    for (int kb = 0; kb < 352; kb += 32) {
        int k = kb + lane;
        int idx = (k < KTAPS) ? row[k] : N;
        bool valid = idx < N;
        unsigned m = __ballot_sync(0xffffffffu, valid);
        if (valid) {
            int pos = cnt + __popc(m & ((1u << lane) - 1));
            list[pos] = (idx << 9) | k;
        }
        cnt += __popc(m);
    }
    int cnt16 = (cnt + 15) & ~15;
    if (lane < cnt16 - cnt) list[cnt + lane] = (N << 9);   // pad: zero row, tap 0
    __syncwarp();

    // ---- phase 2: 16 taps per iteration, 8 LDG.128 in flight ----
    const uint4* xh4 = (const uint4*)g_xh;    // [N+1][8] uint4 rows
    const uint4* w14 = (const uint4*)g_w1h;   // [343][8]

    float acc[8];
    #pragma unroll
    for (int j = 0; j < 8; ++j) acc[j] = 0.f;

    #pragma unroll 1
    for (int c = 0; c < cnt16; c += 16) {
        int e0 = list[c + grp];
        int e1 = list[c + 4 + grp];
        int e2 = list[c + 8 + grp];
        int e3 = list[c + 12 + grp];
        uint4 f0 = xh4[(size_t)(e0 >> 9) * 8 + sub];
        uint4 f1 = xh4[(size_t)(e1 >> 9) * 8 + sub];
        uint4 f2 = xh4[(size_t)(e2 >> 9) * 8 + sub];
        uint4 f3 = xh4[(size_t)(e3 >> 9) * 8 + sub];
        uint4 w0 = w14[(e0 & 511) * 8 + sub];
        uint4 w1 = w14[(e1 & 511) * 8 + sub];
        uint4 w2 = w14[(e2 & 511) * 8 + sub];
        uint4 w3 = w14[(e3 & 511) * 8 + sub];
        accum8(acc, f0, w0);
        accum8(acc, f1, w1);
        accum8(acc, f2, w2);
        accum8(acc, f3, w3);
    }

    // ---- reduce across the 4 tap groups ----
    #pragma unroll
    for (int j = 0; j < 8; ++j) {
        acc[j] += __shfl_xor_sync(0xffffffffu, acc[j], 8);
        acc[j] += __shfl_xor_sync(0xffffffffu, acc[j], 16);
    }

    // ---- bias ----
    {
        float4 ba = ((const float4*)b1)[sub * 2];
        float4 bb = ((const float4*)b1)[sub * 2 + 1];
        acc[0] += ba.x; acc[1] += ba.y; acc[2] += ba.z; acc[3] += ba.w;
        acc[4] += bb.x; acc[5] += bb.y; acc[6] += bb.z; acc[7] += bb.w;
    }

    // ---- GroupNorm over 64 channels (sum within 8-lane group) ----
    float s = 0.f, s2 = 0.f;
    #pragma unroll
    for (int j = 0; j < 8; ++j) { s += acc[j]; s2 += acc[j] * acc[j]; }
    #pragma unroll
    for (int o = 1; o < 8; o <<= 1) {
        s  += __shfl_xor_sync(0xffffffffu, s,  o);
        s2 += __shfl_xor_sync(0xffffffffu, s2, o);
    }
    float mu  = s  * (1.f / 64.f);
    float var = s2 * (1.f / 64.f) - mu * mu;
    float inv = rsqrtf(var + 1e-5f);

    float4 ga = ((const float4*)gamma)[sub * 2];
    float4 gb = ((const float4*)gamma)[sub * 2 + 1];
    float4 ea = ((const float4*)beta)[sub * 2];
    float4 eb = ((const float4*)beta)[sub * 2 + 1];

    float o0 = (acc[0] - mu) * inv * ga.x + ea.x;
    float o1 = (acc[1] - mu) * inv * ga.y + ea.y;
    float o2 = (acc[2] - mu) * inv * ga.z + ea.z;
    float o3 = (acc[3] - mu) * inv * ga.w + ea.w;
    float o4 = (acc[4] - mu) * inv * gb.x + eb.x;
    float o5 = (acc[5] - mu) * inv * gb.y + eb.y;
    float o6 = (acc[6] - mu) * inv * gb.z + eb.z;
    float o7 = (acc[7] - mu) * inv * gb.w + eb.w;

    if (grp == 0) {
        uint4 v;
        v.x = pack_f16x2(o0, o1);
        v.y = pack_f16x2(o2, o3);
        v.z = pack_f16x2(o4, o5);
        v.w = pack_f16x2(o6, o7);
        ((uint4*)g_hh)[(size_t)i * 8 + sub] = v;
    }
}

// ---------------------------------------------------------------------------
// Kernel 2: fp16 tensor-core MLP. 128 voxels/CTA, 8 warps (16 rows each).
// Lane-major fragment weights -> conflict-free LDS.128 (2 loads per 4 MMAs).
// ---------------------------------------------------------------------------
#define XSTR  72    // sX row stride (halfs)
#define OF_X    0
#define OF_W2F  18432                   // 128*72*2
#define OF_W3F  (OF_W2F + 32768)        // 51200
#define OF_B2   (OF_W3F + 32768)        // 83968
#define OF_B3   (OF_B2 + 1024)          // 84992
#define SMEM_SZ (OF_B3 + 256)           // 85248 bytes

__global__ __launch_bounds__(256)
void mlp_f16_kernel(const float* __restrict__ x_feat,
                    const float* __restrict__ b2,
                    const float* __restrict__ b3,
                    float* __restrict__ out, int N) {
    extern __shared__ char sm[];
    __half* sX   = (__half*)(sm + OF_X);
    uint4*  sW2f = (uint4*)(sm + OF_W2F);
    uint4*  sW3f = (uint4*)(sm + OF_W3F);
    float*  sB2  = (float*)(sm + OF_B2);
    float*  sB3  = (float*)(sm + OF_B3);

    const int t  = threadIdx.x;
    const int v0 = blockIdx.x * TILE_M;

    // ---- stage X tile (fp16, zero-pad beyond N) ----
    {
        const uint4* src = (const uint4*)g_hh;
        #pragma unroll
        for (int it = 0; it < 4; ++it) {
            int idx = t + it * 256;             // 0..1023 uint4 (8 halfs each)
            int row = idx >> 3, c8 = idx & 7;
            uint4 v = make_uint4(0, 0, 0, 0);
            if (v0 + row < N) v = src[(size_t)(v0 + row) * 8 + c8];
            *(uint4*)(sX + row * XSTR + c8 * 8) = v;
        }
    }
    // ---- stage fragment weights (straight copies) ----
    #pragma unroll
    for (int it = 0; it < 8; ++it) sW2f[t + it * 256] = g_w2f[t + it * 256];
    #pragma unroll
    for (int it = 0; it < 8; ++it) sW3f[t + it * 256] = g_w3f[t + it * 256];
    sB2[t] = b2[t];
    if (t < 64) sB3[t] = b3[t];
    __syncthreads();

    const int wid = t >> 5, lane = t & 31;
    const int g = lane >> 2, q = lane & 3;
    const int R0 = wid * 16;

    // ---- A fragments of GEMM1 (K=64 -> 4 k-steps of 16), loaded once ----
    uint32_t A1[4][4];
    {
        const __half* xb = sX + (R0 + g) * XSTR + 2 * q;
        #pragma unroll
        for (int ks = 0; ks < 4; ++ks) {
            A1[ks][0] = *(const uint32_t*)(xb + 16 * ks);
            A1[ks][1] = *(const uint32_t*)(xb + 16 * ks + 8 * XSTR);
            A1[ks][2] = *(const uint32_t*)(xb + 16 * ks + 8);
            A1[ks][3] = *(const uint32_t*)(xb + 16 * ks + 8 * XSTR + 8);
        }
    }

    float acc2[8][4];
    #pragma unroll
    for (int n = 0; n < 8; ++n)
        { acc2[n][0] = acc2[n][1] = acc2[n][2] = acc2[n][3] = 0.f; }

    #pragma unroll 1
    for (int ch = 0; ch < 4; ++ch) {
        // ---- GEMM1 chunk: acc1[16 x 64] ----
        float acc1[8][4];
        #pragma unroll
        for (int n = 0; n < 8; ++n)
            { acc1[n][0] = acc1[n][1] = acc1[n][2] = acc1[n][3] = 0.f; }

        #pragma unroll
        for (int nt = 0; nt < 8; ++nt) {
            const uint4* f = sW2f + (ch * 8 + nt) * 64 + lane;
            uint4 u0 = f[0], u1 = f[32];
            MMA_F16(acc1[nt], A1[0], u0.x, u0.y);
            MMA_F16(acc1[nt], A1[1], u0.z, u0.w);
            MMA_F16(acc1[nt], A1[2], u1.x, u1.y);
            MMA_F16(acc1[nt], A1[3], u1.z, u1.w);
        }

        // ---- bias + fast GELU + pack to fp16 (= GEMM2 A fragments) ----
        const int cb = ch * 64;
        uint32_t H2[8], H2B[8];
        #pragma unroll
        for (int nt = 0; nt < 8; ++nt) {
            float2 bv = *(const float2*)(sB2 + cb + nt * 8 + 2 * q);
            float g0 = gelu_fast(acc1[nt][0] + bv.x);
            float g1 = gelu_fast(acc1[nt][1] + bv.y);
            float g2 = gelu_fast(acc1[nt][2] + bv.x);
            float g3 = gelu_fast(acc1[nt][3] + bv.y);
            H2[nt]  = pack_f16x2(g0, g1);
            H2B[nt] = pack_f16x2(g2, g3);
        }

        // ---- GEMM2 partial: acc2 += G_chunk[128x64] @ W3[cb:cb+64, :] ----
        #pragma unroll
        for (int nt2 = 0; nt2 < 8; ++nt2) {
            const uint4* f3 = sW3f + (ch * 8 + nt2) * 64 + lane;
            uint4 u0 = f3[0], u1 = f3[32];
            uint32_t a0[4] = { H2[0], H2B[0], H2[1], H2B[1] };
            uint32_t a1[4] = { H2[2], H2B[2], H2[3], H2B[3] };
            uint32_t a2[4] = { H2[4], H2B[4], H2[5], H2B[5] };
            uint32_t a3[4] = { H2[6], H2B[6], H2[7], H2B[7] };
            MMA_F16(acc2[nt2], a0, u0.x, u0.y);
            MMA_F16(acc2[nt2], a1, u0.z, u0.w);
            MMA_F16(acc2[nt2], a2, u1.x, u1.y);
            MMA_F16(acc2[nt2], a3, u1.z, u1.w);
        }
    }

    // ---- epilogue: + b3 + residual, store ----
    {
        const int v_lo = v0 + R0 + g;
        const int v_hi = v_lo + 8;
        #pragma unroll
        for (int nt2 = 0; nt2 < 8; ++nt2) {
            int col = nt2 * 8 + 2 * q;
            float2 bv = *(const float2*)(sB3 + col);
            if (v_lo < N) {
                float2 xr = *(const float2*)(x_feat + (size_t)v_lo * 64 + col);
                float2 o;
                o.x = acc2[nt2][0] + bv.x + xr.x;
                o.y = acc2[nt2][1] + bv.y + xr.y;
                *(float2*)(out + (size_t)v_lo * 64 + col) = o;
            }
            if (v_hi < N) {
                float2 xr = *(const float2*)(x_feat + (size_t)v_hi * 64 + col);
                float2 o;
                o.x = acc2[nt2][2] + bv.x + xr.x;
                o.y = acc2[nt2][3] + bv.y + xr.y;
                *(float2*)(out + (size_t)v_hi * 64 + col) = o;
            }
        }
    }
}

// ---------------------------------------------------------------------------
extern "C" void kernel_launch(void* const* d_in, const int* in_sizes, int n_in,
                              void* d_out, int out_size) {
    const float* x_feat = (const float*)d_in[0];
    const int*   nbr    = (const int*)  d_in[1];
    const float* W1     = (const float*)d_in[2];
    const float* b1     = (const float*)d_in[3];
    const float* gamma  = (const float*)d_in[4];
    const float* beta   = (const float*)d_in[5];
    const float* W2     = (const float*)d_in[6];
    const float* b2     = (const float*)d_in[7];
    const float* W3     = (const float*)d_in[8];
    const float* b3     = (const float*)d_in[9];
    float* out = (float*)d_out;

    int N = in_sizes[0] / C;
    int tiles = (N + TILE_M - 1) / TILE_M;

    static int smem_set = 0;
    if (!smem_set) {
        cudaFuncSetAttribute(mlp_f16_kernel, cudaFuncAttributeMaxDynamicSharedMemorySize, SMEM_SZ);
        smem_set = 1;
    }

    int prep_elems = (N + 1) * 8 + KTAPS * 8 + 2048 + 2048;
    prep_kernel<<<(prep_elems + 255) / 256, 256>>>(x_feat, W1, W2, W3, N);

    int blocks1 = (N + DW_WARPS - 1) / DW_WARPS;
    dwconv_gn_kernel<<<blocks1, 256>>>(nbr, b1, gamma, beta, N);

    mlp_f16_kernel<<<tiles, 256, SMEM_SZ>>>(x_feat, b2, b3, out, N);
}

// round 15
// speedup vs baseline: 1.0937x; 1.0937x over previous
#include <cuda_runtime.h>
#include <cuda_fp16.h>
#include <math.h>
#include <stdint.h>

#define NMAX   100000
#define C      64
#define KTAPS  343
#define TILE_M 128

// ---------------------------------------------------------------------------
// device scratch (no cudaMalloc allowed)
// ---------------------------------------------------------------------------
__device__ __align__(16) __half2 g_xh[(size_t)(NMAX + 1) * 32]; // x_feat fp16 [N+1][64], row N = zeros
__device__ __align__(16) __half2 g_w1h[KTAPS * 32];             // W1 fp16 [343][64]
__device__ __align__(16) __half  g_hh[(size_t)NMAX * 64];       // h post-GN fp16 [N][64]
__device__ __align__(16) uint4   g_w2f[2048];                   // W2^T fragments, lane-major
__device__ __align__(16) uint4   g_w3f[2048];                   // W3^T fragments, lane-major

__device__ __forceinline__ uint32_t pack_f16x2(float lo, float hi) {
    uint32_t u;
    asm("cvt.rn.f16x2.f32 %0, %1, %2;" : "=r"(u) : "f"(hi), "f"(lo));
    return u;
}

// tanh-form GELU with single-MUFU tanh.approx
__device__ __forceinline__ float gelu_fast(float x) {
    float x2 = x * x;
    float u  = fmaf(0.035677408136f, x2, 0.7978845608028654f);
    float ta = x * u;
    float t;
    asm("tanh.approx.f32 %0, %1;" : "=f"(t) : "f"(ta));
    float hx = 0.5f * x;
    return fmaf(hx, t, hx);
}

// D += A * B   (m16n8k16, f16 inputs, f32 accum; A row frag, B col frag)
#define MMA_F16(d, a, b0, b1)                                                           \
    asm volatile("mma.sync.aligned.m16n8k16.row.col.f32.f16.f16.f32 "                   \
                 "{%0,%1,%2,%3}, {%4,%5,%6,%7}, {%8,%9}, {%0,%1,%2,%3};"                \
                 : "+f"((d)[0]), "+f"((d)[1]), "+f"((d)[2]), "+f"((d)[3])               \
                 : "r"((a)[0]), "r"((a)[1]), "r"((a)[2]), "r"((a)[3]),                  \
                   "r"(b0), "r"(b1))

// ---------------------------------------------------------------------------
// Kernel 0: fp16 conversions + lane-major fragment-ordered weight images
// ---------------------------------------------------------------------------
__global__ void prep_kernel(const float* __restrict__ x,
                            const float* __restrict__ W1,
                            const float* __restrict__ W2,
                            const float* __restrict__ W3, int N) {
    int e = blockIdx.x * blockDim.x + threadIdx.x;
    int nx = (N + 1) * 8;                       // uint4 outputs for x (+ sentinel row)
    if (e < nx) {
        uint4 v = make_uint4(0, 0, 0, 0);
        if ((e >> 3) < N) {
            const float4* s = (const float4*)x + (size_t)e * 2;
            float4 a = s[0], b = s[1];
            v.x = pack_f16x2(a.x, a.y); v.y = pack_f16x2(a.z, a.w);
            v.z = pack_f16x2(b.x, b.y); v.w = pack_f16x2(b.z, b.w);
        }
        ((uint4*)g_xh)[e] = v;
        return;
    }
    int e1 = e - nx;
    if (e1 < KTAPS * 8) {
        const float4* s = (const float4*)W1 + (size_t)e1 * 2;
        float4 a = s[0], b = s[1];
        uint4 v;
        v.x = pack_f16x2(a.x, a.y); v.y = pack_f16x2(a.z, a.w);
        v.z = pack_f16x2(b.x, b.y); v.w = pack_f16x2(b.z, b.w);
        ((uint4*)g_w1h)[e1] = v;
        return;
    }
    int e2 = e1 - KTAPS * 8;
    if (e2 < 2048) {
        // lane-major W2 fragments: idx = (ch*8+nt)*64 + half*32 + lane
        int blk = e2 >> 6, half = (e2 >> 5) & 1, lane = e2 & 31;
        int ch = blk >> 3, nt = blk & 7;
        int g = lane >> 2, q = lane & 3;
        int n  = ch * 64 + nt * 8 + g;          // W2^T row (output unit)
        int kb = 32 * half + 2 * q;
        uint4 v;
        v.x = pack_f16x2(W2[(kb +  0) * 256 + n], W2[(kb +  1) * 256 + n]);
        v.y = pack_f16x2(W2[(kb +  8) * 256 + n], W2[(kb +  9) * 256 + n]);
        v.z = pack_f16x2(W2[(kb + 16) * 256 + n], W2[(kb + 17) * 256 + n]);
        v.w = pack_f16x2(W2[(kb + 24) * 256 + n], W2[(kb + 25) * 256 + n]);
        g_w2f[e2] = v;
        return;
    }
    int e3 = e2 - 2048;
    if (e3 < 2048) {
        // lane-major W3 fragments: idx = (ch*8+nt2)*64 + half*32 + lane
        int blk = e3 >> 6, half = (e3 >> 5) & 1, lane = e3 & 31;
        int ch = blk >> 3, nt2 = blk & 7;
        int g = lane >> 2, q = lane & 3;
        int c  = nt2 * 8 + g;                   // W3^T row (output channel)
        int jb = 32 * (2 * ch + half) + 2 * q;
        uint4 v;
        v.x = pack_f16x2(W3[(jb +  0) * 64 + c], W3[(jb +  1) * 64 + c]);
        v.y = pack_f16x2(W3[(jb +  8) * 64 + c], W3[(jb +  9) * 64 + c]);
        v.z = pack_f16x2(W3[(jb + 16) * 64 + c], W3[(jb + 17) * 64 + c]);
        v.w = pack_f16x2(W3[(jb + 24) * 64 + c], W3[(jb + 25) * 64 + c]);
        g_w3f[e3] = v;
    }
}

// ---------------------------------------------------------------------------
// Kernel 1: depthwise submanifold conv + bias + GroupNorm
// one warp per voxel; compacted tap list; 8 taps/iter (4 LDG.128 in flight);
// pairwise HFMA2 accumulation, dumped to fp32 every iteration (2 products).
// ---------------------------------------------------------------------------
#define DW_WARPS 8

__global__ __launch_bounds__(256)
void dwconv_gn_kernel(const int*   __restrict__ nbr,
                      const float* __restrict__ b1,
                      const float* __restrict__ gamma,
                      const float* __restrict__ beta,
                      int N) {
    __shared__ int s_list[DW_WARPS][352];

    const int wslot = threadIdx.x >> 5;
    const int lane  = threadIdx.x & 31;
    const int grp   = lane >> 3;     // tap slot 0..3
    const int sub   = lane & 7;      // channel slice (8 ch)
    const int i = blockIdx.x * DW_WARPS + wslot;
    if (i >= N) return;

    const int* row = nbr + (long long)i * KTAPS;
    int* list = s_list[wslot];

    // ---- phase 1: compact valid (src, tap) into smem list ----
    int cnt = 0;
    #pragma unroll
    for (int kb = 0; kb < 352; kb += 32) {
        int k = kb + lane;
        int idx = (k < KTAPS) ? row[k] : N;
        bool valid = idx < N;
        unsigned m = __ballot_sync(0xffffffffu, valid);
        if (valid) {
            int pos = cnt + __popc(m & ((1u << lane) - 1));
            list[pos] = (idx << 9) | k;
        }
        cnt += __popc(m);
    }
    int cnt8 = (cnt + 7) & ~7;
    if (lane < cnt8 - cnt) list[cnt + lane] = (N << 9);   // pad: zero row, tap 0
    __syncwarp();

    // ---- phase 2: 8 taps per iteration, 4 LDG.128 in flight,
    //      pairwise HFMA2 then fp32 dump (2 fp16 products per slot) ----
    const uint4* xh4 = (const uint4*)g_xh;    // [N+1][8] uint4 rows
    const uint4* w14 = (const uint4*)g_w1h;   // [343][8]

    float acc[8];
    #pragma unroll
    for (int j = 0; j < 8; ++j) acc[j] = 0.f;

    #pragma unroll 1
    for (int c = 0; c < cnt8; c += 8) {
        int e0 = list[c + grp];
        int e1 = list[c + 4 + grp];
        uint4 f0 = xh4[(size_t)(e0 >> 9) * 8 + sub];
        uint4 f1 = xh4[(size_t)(e1 >> 9) * 8 + sub];
        uint4 w0 = w14[(e0 & 511) * 8 + sub];
        uint4 w1 = w14[(e1 & 511) * 8 + sub];
        const __half2* fh0 = (const __half2*)&f0;
        const __half2* wh0 = (const __half2*)&w0;
        const __half2* fh1 = (const __half2*)&f1;
        const __half2* wh1 = (const __half2*)&w1;
        #pragma unroll
        for (int m = 0; m < 4; ++m) {
            __half2 p = __hmul2(fh0[m], wh0[m]);          // product tap e0
            p = __hfma2(fh1[m], wh1[m], p);               // + product tap e1 (fp16)
            float2 pf = __half22float2(p);                // dump to fp32
            acc[2 * m]     += pf.x;
            acc[2 * m + 1] += pf.y;
        }
    }

    // ---- reduce across the 4 tap groups ----
    #pragma unroll
    for (int j = 0; j < 8; ++j) {
        acc[j] += __shfl_xor_sync(0xffffffffu, acc[j], 8);
        acc[j] += __shfl_xor_sync(0xffffffffu, acc[j], 16);
    }

    // ---- bias ----
    {
        float4 ba = ((const float4*)b1)[sub * 2];
        float4 bb = ((const float4*)b1)[sub * 2 + 1];
        acc[0] += ba.x; acc[1] += ba.y; acc[2] += ba.z; acc[3] += ba.w;
        acc[4] += bb.x; acc[5] += bb.y; acc[6] += bb.z; acc[7] += bb.w;
    }

    // ---- GroupNorm over 64 channels (sum within 8-lane group) ----
    float s = 0.f, s2 = 0.f;
    #pragma unroll
    for (int j = 0; j < 8; ++j) { s += acc[j]; s2 += acc[j] * acc[j]; }
    #pragma unroll
    for (int o = 1; o < 8; o <<= 1) {
        s  += __shfl_xor_sync(0xffffffffu, s,  o);
        s2 += __shfl_xor_sync(0xffffffffu, s2, o);
    }
    float mu  = s  * (1.f / 64.f);
    float var = s2 * (1.f / 64.f) - mu * mu;
    float inv = rsqrtf(var + 1e-5f);

    float4 ga = ((const float4*)gamma)[sub * 2];
    float4 gb = ((const float4*)gamma)[sub * 2 + 1];
    float4 ea = ((const float4*)beta)[sub * 2];
    float4 eb = ((const float4*)beta)[sub * 2 + 1];

    float o0 = (acc[0] - mu) * inv * ga.x + ea.x;
    float o1 = (acc[1] - mu) * inv * ga.y + ea.y;
    float o2 = (acc[2] - mu) * inv * ga.z + ea.z;
    float o3 = (acc[3] - mu) * inv * ga.w + ea.w;
    float o4 = (acc[4] - mu) * inv * gb.x + eb.x;
    float o5 = (acc[5] - mu) * inv * gb.y + eb.y;
    float o6 = (acc[6] - mu) * inv * gb.z + eb.z;
    float o7 = (acc[7] - mu) * inv * gb.w + eb.w;

    if (grp == 0) {
        uint4 v;
        v.x = pack_f16x2(o0, o1);
        v.y = pack_f16x2(o2, o3);
        v.z = pack_f16x2(o4, o5);
        v.w = pack_f16x2(o6, o7);
        ((uint4*)g_hh)[(size_t)i * 8 + sub] = v;
    }
}

// ---------------------------------------------------------------------------
// Kernel 2: fp16 tensor-core MLP. 128 voxels/CTA, 8 warps (16 rows each).
// Lane-major fragment weights -> conflict-free LDS.128 (2 loads per 4 MMAs).
// ---------------------------------------------------------------------------
#define XSTR  72    // sX row stride (halfs)
#define OF_X    0
#define OF_W2F  18432                   // 128*72*2
#define OF_W3F  (OF_W2F + 32768)        // 51200
#define OF_B2   (OF_W3F + 32768)        // 83968
#define OF_B3   (OF_B2 + 1024)          // 84992
#define SMEM_SZ (OF_B3 + 256)           // 85248 bytes

__global__ __launch_bounds__(256)
void mlp_f16_kernel(const float* __restrict__ x_feat,
                    const float* __restrict__ b2,
                    const float* __restrict__ b3,
                    float* __restrict__ out, int N) {
    extern __shared__ char sm[];
    __half* sX   = (__half*)(sm + OF_X);
    uint4*  sW2f = (uint4*)(sm + OF_W2F);
    uint4*  sW3f = (uint4*)(sm + OF_W3F);
    float*  sB2  = (float*)(sm + OF_B2);
    float*  sB3  = (float*)(sm + OF_B3);

    const int t  = threadIdx.x;
    const int v0 = blockIdx.x * TILE_M;

    // ---- stage X tile (fp16, zero-pad beyond N) ----
    {
        const uint4* src = (const uint4*)g_hh;
        #pragma unroll
        for (int it = 0; it < 4; ++it) {
            int idx = t + it * 256;             // 0..1023 uint4 (8 halfs each)
            int row = idx >> 3, c8 = idx & 7;
            uint4 v = make_uint4(0, 0, 0, 0);
            if (v0 + row < N) v = src[(size_t)(v0 + row) * 8 + c8];
            *(uint4*)(sX + row * XSTR + c8 * 8) = v;
        }
    }
    // ---- stage fragment weights (straight copies) ----
    #pragma unroll
    for (int it = 0; it < 8; ++it) sW2f[t + it * 256] = g_w2f[t + it * 256];
    #pragma unroll
    for (int it = 0; it < 8; ++it) sW3f[t + it * 256] = g_w3f[t + it * 256];
    sB2[t] = b2[t];
    if (t < 64) sB3[t] = b3[t];
    __syncthreads();

    const int wid = t >> 5, lane = t & 31;
    const int g = lane >> 2, q = lane & 3;
    const int R0 = wid * 16;

    // ---- A fragments of GEMM1 (K=64 -> 4 k-steps of 16), loaded once ----
    uint32_t A1[4][4];
    {
        const __half* xb = sX + (R0 + g) * XSTR + 2 * q;
        #pragma unroll
        for (int ks = 0; ks < 4; ++ks) {
            A1[ks][0] = *(const uint32_t*)(xb + 16 * ks);
            A1[ks][1] = *(const uint32_t*)(xb + 16 * ks + 8 * XSTR);
            A1[ks][2] = *(const uint32_t*)(xb + 16 * ks + 8);
            A1[ks][3] = *(const uint32_t*)(xb + 16 * ks + 8 * XSTR + 8);
        }
    }

    float acc2[8][4];
    #pragma unroll
    for (int n = 0; n < 8; ++n)
        { acc2[n][0] = acc2[n][1] = acc2[n][2] = acc2[n][3] = 0.f; }

    #pragma unroll 1
    for (int ch = 0; ch < 4; ++ch) {
        // ---- GEMM1 chunk: acc1[16 x 64] ----
        float acc1[8][4];
        #pragma unroll
        for (int n = 0; n < 8; ++n)
            { acc1[n][0] = acc1[n][1] = acc1[n][2] = acc1[n][3] = 0.f; }

        #pragma unroll
        for (int nt = 0; nt < 8; ++nt) {
            const uint4* f = sW2f + (ch * 8 + nt) * 64 + lane;
            uint4 u0 = f[0], u1 = f[32];
            MMA_F16(acc1[nt], A1[0], u0.x, u0.y);
            MMA_F16(acc1[nt], A1[1], u0.z, u0.w);
            MMA_F16(acc1[nt], A1[2], u1.x, u1.y);
            MMA_F16(acc1[nt], A1[3], u1.z, u1.w);
        }

        // ---- bias + fast GELU + pack to fp16 (= GEMM2 A fragments) ----
        const int cb = ch * 64;
        uint32_t H2[8], H2B[8];
        #pragma unroll
        for (int nt = 0; nt < 8; ++nt) {
            float2 bv = *(const float2*)(sB2 + cb + nt * 8 + 2 * q);
            float g0 = gelu_fast(acc1[nt][0] + bv.x);
            float g1 = gelu_fast(acc1[nt][1] + bv.y);
            float g2 = gelu_fast(acc1[nt][2] + bv.x);
            float g3 = gelu_fast(acc1[nt][3] + bv.y);
            H2[nt]  = pack_f16x2(g0, g1);
            H2B[nt] = pack_f16x2(g2, g3);
        }

        // ---- GEMM2 partial: acc2 += G_chunk[128x64] @ W3[cb:cb+64, :] ----
        #pragma unroll
        for (int nt2 = 0; nt2 < 8; ++nt2) {
            const uint4* f3 = sW3f + (ch * 8 + nt2) * 64 + lane;
            uint4 u0 = f3[0], u1 = f3[32];
            uint32_t a0[4] = { H2[0], H2B[0], H2[1], H2B[1] };
            uint32_t a1[4] = { H2[2], H2B[2], H2[3], H2B[3] };
            uint32_t a2[4] = { H2[4], H2B[4], H2[5], H2B[5] };
            uint32_t a3[4] = { H2[6], H2B[6], H2[7], H2B[7] };
            MMA_F16(acc2[nt2], a0, u0.x, u0.y);
            MMA_F16(acc2[nt2], a1, u0.z, u0.w);
            MMA_F16(acc2[nt2], a2, u1.x, u1.y);
            MMA_F16(acc2[nt2], a3, u1.z, u1.w);
        }
    }

    // ---- epilogue: + b3 + residual, store ----
    {
        const int v_lo = v0 + R0 + g;
        const int v_hi = v_lo + 8;
        #pragma unroll
        for (int nt2 = 0; nt2 < 8; ++nt2) {
            int col = nt2 * 8 + 2 * q;
            float2 bv = *(const float2*)(sB3 + col);
            if (v_lo < N) {
                float2 xr = *(const float2*)(x_feat + (size_t)v_lo * 64 + col);
                float2 o;
                o.x = acc2[nt2][0] + bv.x + xr.x;
                o.y = acc2[nt2][1] + bv.y + xr.y;
                *(float2*)(out + (size_t)v_lo * 64 + col) = o;
            }
            if (v_hi < N) {
                float2 xr = *(const float2*)(x_feat + (size_t)v_hi * 64 + col);
                float2 o;
                o.x = acc2[nt2][2] + bv.x + xr.x;
                o.y = acc2[nt2][3] + bv.y + xr.y;
                *(float2*)(out + (size_t)v_hi * 64 + col) = o;
            }
        }
    }
}

// ---------------------------------------------------------------------------
extern "C" void kernel_launch(void* const* d_in, const int* in_sizes, int n_in,
                              void* d_out, int out_size) {
    const float* x_feat = (const float*)d_in[0];
    const int*   nbr    = (const int*)  d_in[1];
    const float* W1     = (const float*)d_in[2];
    const float* b1     = (const float*)d_in[3];
    const float* gamma  = (const float*)d_in[4];
    const float* beta   = (const float*)d_in[5];
    const float* W2     = (const float*)d_in[6];
    const float* b2     = (const float*)d_in[7];
    const float* W3     = (const float*)d_in[8];
    const float* b3     = (const float*)d_in[9];
    float* out = (float*)d_out;

    int N = in_sizes[0] / C;
    int tiles = (N + TILE_M - 1) / TILE_M;

    static int smem_set = 0;
    if (!smem_set) {
        cudaFuncSetAttribute(mlp_f16_kernel, cudaFuncAttributeMaxDynamicSharedMemorySize, SMEM_SZ);
        smem_set = 1;
    }

    int prep_elems = (N + 1) * 8 + KTAPS * 8 + 2048 + 2048;
    prep_kernel<<<(prep_elems + 255) / 256, 256>>>(x_feat, W1, W2, W3, N);

    int blocks1 = (N + DW_WARPS - 1) / DW_WARPS;
    dwconv_gn_kernel<<<blocks1, 256>>>(nbr, b1, gamma, beta, N);

    mlp_f16_kernel<<<tiles, 256, SMEM_SZ>>>(x_feat, b2, b3, out, N);
}

// round 16
// speedup vs baseline: 1.1083x; 1.0134x over previous
#include <cuda_runtime.h>
#include <cuda_fp16.h>
#include <math.h>
#include <stdint.h>

#define NMAX   100000
#define C      64
#define KTAPS  343
#define TILE_M 128

// ---------------------------------------------------------------------------
// device scratch (no cudaMalloc allowed)
// ---------------------------------------------------------------------------
__device__ __align__(16) __half2 g_xh[(size_t)(NMAX + 1) * 32]; // x_feat fp16 [N+1][64], row N = zeros
__device__ __align__(16) __half2 g_w1h[KTAPS * 32];             // W1 fp16 [343][64]
__device__ __align__(16) __half  g_hh[(size_t)NMAX * 64];       // h post-GN fp16 [N][64]
__device__ __align__(16) uint4   g_w2f[2048];                   // W2^T fragments, lane-major
__device__ __align__(16) uint4   g_w3f[2048];                   // W3^T fragments, lane-major

__device__ __forceinline__ uint32_t pack_f16x2(float lo, float hi) {
    uint32_t u;
    asm("cvt.rn.f16x2.f32 %0, %1, %2;" : "=r"(u) : "f"(hi), "f"(lo));
    return u;
}

// tanh-form GELU with single-MUFU tanh.approx
__device__ __forceinline__ float gelu_fast(float x) {
    float x2 = x * x;
    float u  = fmaf(0.035677408136f, x2, 0.7978845608028654f);
    float ta = x * u;
    float t;
    asm("tanh.approx.f32 %0, %1;" : "=f"(t) : "f"(ta));
    float hx = 0.5f * x;
    return fmaf(hx, t, hx);
}

// D += A * B   (m16n8k16, f16 inputs, f32 accum; A row frag, B col frag)
#define MMA_F16(d, a, b0, b1)                                                           \
    asm volatile("mma.sync.aligned.m16n8k16.row.col.f32.f16.f16.f32 "                   \
                 "{%0,%1,%2,%3}, {%4,%5,%6,%7}, {%8,%9}, {%0,%1,%2,%3};"                \
                 : "+f"((d)[0]), "+f"((d)[1]), "+f"((d)[2]), "+f"((d)[3])               \
                 : "r"((a)[0]), "r"((a)[1]), "r"((a)[2]), "r"((a)[3]),                  \
                   "r"(b0), "r"(b1))

// ---------------------------------------------------------------------------
// Kernel 0: fp16 conversions + lane-major fragment-ordered weight images
// ---------------------------------------------------------------------------
__global__ void prep_kernel(const float* __restrict__ x,
                            const float* __restrict__ W1,
                            const float* __restrict__ W2,
                            const float* __restrict__ W3, int N) {
    int e = blockIdx.x * blockDim.x + threadIdx.x;
    int nx = (N + 1) * 8;                       // uint4 outputs for x (+ sentinel row)
    if (e < nx) {
        uint4 v = make_uint4(0, 0, 0, 0);
        if ((e >> 3) < N) {
            const float4* s = (const float4*)x + (size_t)e * 2;
            float4 a = s[0], b = s[1];
            v.x = pack_f16x2(a.x, a.y); v.y = pack_f16x2(a.z, a.w);
            v.z = pack_f16x2(b.x, b.y); v.w = pack_f16x2(b.z, b.w);
        }
        ((uint4*)g_xh)[e] = v;
        return;
    }
    int e1 = e - nx;
    if (e1 < KTAPS * 8) {
        const float4* s = (const float4*)W1 + (size_t)e1 * 2;
        float4 a = s[0], b = s[1];
        uint4 v;
        v.x = pack_f16x2(a.x, a.y); v.y = pack_f16x2(a.z, a.w);
        v.z = pack_f16x2(b.x, b.y); v.w = pack_f16x2(b.z, b.w);
        ((uint4*)g_w1h)[e1] = v;
        return;
    }
    int e2 = e1 - KTAPS * 8;
    if (e2 < 2048) {
        // lane-major W2 fragments: idx = (ch*8+nt)*64 + half*32 + lane
        int blk = e2 >> 6, half = (e2 >> 5) & 1, lane = e2 & 31;
        int ch = blk >> 3, nt = blk & 7;
        int g = lane >> 2, q = lane & 3;
        int n  = ch * 64 + nt * 8 + g;          // W2^T row (output unit)
        int kb = 32 * half + 2 * q;
        uint4 v;
        v.x = pack_f16x2(W2[(kb +  0) * 256 + n], W2[(kb +  1) * 256 + n]);
        v.y = pack_f16x2(W2[(kb +  8) * 256 + n], W2[(kb +  9) * 256 + n]);
        v.z = pack_f16x2(W2[(kb + 16) * 256 + n], W2[(kb + 17) * 256 + n]);
        v.w = pack_f16x2(W2[(kb + 24) * 256 + n], W2[(kb + 25) * 256 + n]);
        g_w2f[e2] = v;
        return;
    }
    int e3 = e2 - 2048;
    if (e3 < 2048) {
        // lane-major W3 fragments: idx = (ch*8+nt2)*64 + half*32 + lane
        int blk = e3 >> 6, half = (e3 >> 5) & 1, lane = e3 & 31;
        int ch = blk >> 3, nt2 = blk & 7;
        int g = lane >> 2, q = lane & 3;
        int c  = nt2 * 8 + g;                   // W3^T row (output channel)
        int jb = 32 * (2 * ch + half) + 2 * q;
        uint4 v;
        v.x = pack_f16x2(W3[(jb +  0) * 64 + c], W3[(jb +  1) * 64 + c]);
        v.y = pack_f16x2(W3[(jb +  8) * 64 + c], W3[(jb +  9) * 64 + c]);
        v.z = pack_f16x2(W3[(jb + 16) * 64 + c], W3[(jb + 17) * 64 + c]);
        v.w = pack_f16x2(W3[(jb + 24) * 64 + c], W3[(jb + 25) * 64 + c]);
        g_w3f[e3] = v;
    }
}

// ---------------------------------------------------------------------------
// Kernel 1: depthwise submanifold conv + bias + GroupNorm
// one warp per voxel; compacted tap list; 8 taps/iter (4 LDG.128 in flight);
// full-loop fp16 HFMA2 accumulation (8 arith issues/iter), fp32 convert once.
// ---------------------------------------------------------------------------
#define DW_WARPS 8

__global__ __launch_bounds__(256)
void dwconv_gn_kernel(const int*   __restrict__ nbr,
                      const float* __restrict__ b1,
                      const float* __restrict__ gamma,
                      const float* __restrict__ beta,
                      int N) {
    __shared__ int s_list[DW_WARPS][352];

    const int wslot = threadIdx.x >> 5;
    const int lane  = threadIdx.x & 31;
    const int grp   = lane >> 3;     // tap slot 0..3
    const int sub   = lane & 7;      // channel slice (8 ch)
    const int i = blockIdx.x * DW_WARPS + wslot;
    if (i >= N) return;

    const int* row = nbr + (long long)i * KTAPS;
    int* list = s_list[wslot];

    // ---- phase 1: compact valid (src, tap) into smem list ----
    int cnt = 0;
    #pragma unroll
    for (int kb = 0; kb < 352; kb += 32) {
        int k = kb + lane;
        int idx = (k < KTAPS) ? row[k] : N;
        bool valid = idx < N;
        unsigned m = __ballot_sync(0xffffffffu, valid);
        if (valid) {
            int pos = cnt + __popc(m & ((1u << lane) - 1));
            list[pos] = (idx << 9) | k;
        }
        cnt += __popc(m);
    }
    int cnt8 = (cnt + 7) & ~7;
    if (lane < cnt8 - cnt) list[cnt + lane] = (N << 9);   // pad: zero row, tap 0
    __syncwarp();

    // ---- phase 2: 8 taps per iteration, 4 LDG.128 in flight,
    //      fp16 HFMA2 accumulation across the whole loop ----
    const uint4* xh4 = (const uint4*)g_xh;    // [N+1][8] uint4 rows
    const uint4* w14 = (const uint4*)g_w1h;   // [343][8]

    __half2 ah[4];
    ah[0] = __floats2half2_rn(0.f, 0.f);
    ah[1] = ah[0]; ah[2] = ah[0]; ah[3] = ah[0];

    #pragma unroll 1
    for (int c = 0; c < cnt8; c += 8) {
        int e0 = list[c + grp];
        int e1 = list[c + 4 + grp];
        uint4 f0 = xh4[(size_t)(e0 >> 9) * 8 + sub];
        uint4 f1 = xh4[(size_t)(e1 >> 9) * 8 + sub];
        uint4 w0 = w14[(e0 & 511) * 8 + sub];
        uint4 w1 = w14[(e1 & 511) * 8 + sub];
        const __half2* fh0 = (const __half2*)&f0;
        const __half2* wh0 = (const __half2*)&w0;
        const __half2* fh1 = (const __half2*)&f1;
        const __half2* wh1 = (const __half2*)&w1;
        #pragma unroll
        for (int m = 0; m < 4; ++m) {
            ah[m] = __hfma2(fh0[m], wh0[m], ah[m]);
            ah[m] = __hfma2(fh1[m], wh1[m], ah[m]);
        }
    }

    // ---- convert to fp32 once ----
    float acc[8];
    #pragma unroll
    for (int m = 0; m < 4; ++m) {
        float2 pf = __half22float2(ah[m]);
        acc[2 * m]     = pf.x;
        acc[2 * m + 1] = pf.y;
    }

    // ---- reduce across the 4 tap groups (fp32) ----
    #pragma unroll
    for (int j = 0; j < 8; ++j) {
        acc[j] += __shfl_xor_sync(0xffffffffu, acc[j], 8);
        acc[j] += __shfl_xor_sync(0xffffffffu, acc[j], 16);
    }

    // ---- bias ----
    {
        float4 ba = ((const float4*)b1)[sub * 2];
        float4 bb = ((const float4*)b1)[sub * 2 + 1];
        acc[0] += ba.x; acc[1] += ba.y; acc[2] += ba.z; acc[3] += ba.w;
        acc[4] += bb.x; acc[5] += bb.y; acc[6] += bb.z; acc[7] += bb.w;
    }

    // ---- GroupNorm over 64 channels (sum within 8-lane group) ----
    float s = 0.f, s2 = 0.f;
    #pragma unroll
    for (int j = 0; j < 8; ++j) { s += acc[j]; s2 += acc[j] * acc[j]; }
    #pragma unroll
    for (int o = 1; o < 8; o <<= 1) {
        s  += __shfl_xor_sync(0xffffffffu, s,  o);
        s2 += __shfl_xor_sync(0xffffffffu, s2, o);
    }
    float mu  = s  * (1.f / 64.f);
    float var = s2 * (1.f / 64.f) - mu * mu;
    float inv = rsqrtf(var + 1e-5f);

    float4 ga = ((const float4*)gamma)[sub * 2];
    float4 gb = ((const float4*)gamma)[sub * 2 + 1];
    float4 ea = ((const float4*)beta)[sub * 2];
    float4 eb = ((const float4*)beta)[sub * 2 + 1];

    float o0 = (acc[0] - mu) * inv * ga.x + ea.x;
    float o1 = (acc[1] - mu) * inv * ga.y + ea.y;
    float o2 = (acc[2] - mu) * inv * ga.z + ea.z;
    float o3 = (acc[3] - mu) * inv * ga.w + ea.w;
    float o4 = (acc[4] - mu) * inv * gb.x + eb.x;
    float o5 = (acc[5] - mu) * inv * gb.y + eb.y;
    float o6 = (acc[6] - mu) * inv * gb.z + eb.z;
    float o7 = (acc[7] - mu) * inv * gb.w + eb.w;

    if (grp == 0) {
        uint4 v;
        v.x = pack_f16x2(o0, o1);
        v.y = pack_f16x2(o2, o3);
        v.z = pack_f16x2(o4, o5);
        v.w = pack_f16x2(o6, o7);
        ((uint4*)g_hh)[(size_t)i * 8 + sub] = v;
    }
}

// ---------------------------------------------------------------------------
// Kernel 2: fp16 tensor-core MLP. 128 voxels/CTA, 8 warps (16 rows each).
// Lane-major fragment weights -> conflict-free LDS.128 (2 loads per 4 MMAs).
// ---------------------------------------------------------------------------
#define XSTR  72    // sX row stride (halfs)
#define OF_X    0
#define OF_W2F  18432                   // 128*72*2
#define OF_W3F  (OF_W2F + 32768)        // 51200
#define OF_B2   (OF_W3F + 32768)        // 83968
#define OF_B3   (OF_B2 + 1024)          // 84992
#define SMEM_SZ (OF_B3 + 256)           // 85248 bytes

__global__ __launch_bounds__(256)
void mlp_f16_kernel(const float* __restrict__ x_feat,
                    const float* __restrict__ b2,
                    const float* __restrict__ b3,
                    float* __restrict__ out, int N) {
    extern __shared__ char sm[];
    __half* sX   = (__half*)(sm + OF_X);
    uint4*  sW2f = (uint4*)(sm + OF_W2F);
    uint4*  sW3f = (uint4*)(sm + OF_W3F);
    float*  sB2  = (float*)(sm + OF_B2);
    float*  sB3  = (float*)(sm + OF_B3);

    const int t  = threadIdx.x;
    const int v0 = blockIdx.x * TILE_M;

    // ---- stage X tile (fp16, zero-pad beyond N) ----
    {
        const uint4* src = (const uint4*)g_hh;
        #pragma unroll
        for (int it = 0; it < 4; ++it) {
            int idx = t + it * 256;             // 0..1023 uint4 (8 halfs each)
            int row = idx >> 3, c8 = idx & 7;
            uint4 v = make_uint4(0, 0, 0, 0);
            if (v0 + row < N) v = src[(size_t)(v0 + row) * 8 + c8];
            *(uint4*)(sX + row * XSTR + c8 * 8) = v;
        }
    }
    // ---- stage fragment weights (straight copies) ----
    #pragma unroll
    for (int it = 0; it < 8; ++it) sW2f[t + it * 256] = g_w2f[t + it * 256];
    #pragma unroll
    for (int it = 0; it < 8; ++it) sW3f[t + it * 256] = g_w3f[t + it * 256];
    sB2[t] = b2[t];
    if (t < 64) sB3[t] = b3[t];
    __syncthreads();

    const int wid = t >> 5, lane = t & 31;
    const int g = lane >> 2, q = lane & 3;
    const int R0 = wid * 16;

    // ---- A fragments of GEMM1 (K=64 -> 4 k-steps of 16), loaded once ----
    uint32_t A1[4][4];
    {
        const __half* xb = sX + (R0 + g) * XSTR + 2 * q;
        #pragma unroll
        for (int ks = 0; ks < 4; ++ks) {
            A1[ks][0] = *(const uint32_t*)(xb + 16 * ks);
            A1[ks][1] = *(const uint32_t*)(xb + 16 * ks + 8 * XSTR);
            A1[ks][2] = *(const uint32_t*)(xb + 16 * ks + 8);
            A1[ks][3] = *(const uint32_t*)(xb + 16 * ks + 8 * XSTR + 8);
        }
    }

    float acc2[8][4];
    #pragma unroll
    for (int n = 0; n < 8; ++n)
        { acc2[n][0] = acc2[n][1] = acc2[n][2] = acc2[n][3] = 0.f; }

    #pragma unroll 1
    for (int ch = 0; ch < 4; ++ch) {
        // ---- GEMM1 chunk: acc1[16 x 64] ----
        float acc1[8][4];
        #pragma unroll
        for (int n = 0; n < 8; ++n)
            { acc1[n][0] = acc1[n][1] = acc1[n][2] = acc1[n][3] = 0.f; }

        #pragma unroll
        for (int nt = 0; nt < 8; ++nt) {
            const uint4* f = sW2f + (ch * 8 + nt) * 64 + lane;
            uint4 u0 = f[0], u1 = f[32];
            MMA_F16(acc1[nt], A1[0], u0.x, u0.y);
            MMA_F16(acc1[nt], A1[1], u0.z, u0.w);
            MMA_F16(acc1[nt], A1[2], u1.x, u1.y);
            MMA_F16(acc1[nt], A1[3], u1.z, u1.w);
        }

        // ---- bias + fast GELU + pack to fp16 (= GEMM2 A fragments) ----
        const int cb = ch * 64;
        uint32_t H2[8], H2B[8];
        #pragma unroll
        for (int nt = 0; nt < 8; ++nt) {
            float2 bv = *(const float2*)(sB2 + cb + nt * 8 + 2 * q);
            float g0 = gelu_fast(acc1[nt][0] + bv.x);
            float g1 = gelu_fast(acc1[nt][1] + bv.y);
            float g2 = gelu_fast(acc1[nt][2] + bv.x);
            float g3 = gelu_fast(acc1[nt][3] + bv.y);
            H2[nt]  = pack_f16x2(g0, g1);
            H2B[nt] = pack_f16x2(g2, g3);
        }

        // ---- GEMM2 partial: acc2 += G_chunk[128x64] @ W3[cb:cb+64, :] ----
        #pragma unroll
        for (int nt2 = 0; nt2 < 8; ++nt2) {
            const uint4* f3 = sW3f + (ch * 8 + nt2) * 64 + lane;
            uint4 u0 = f3[0], u1 = f3[32];
            uint32_t a0[4] = { H2[0], H2B[0], H2[1], H2B[1] };
            uint32_t a1[4] = { H2[2], H2B[2], H2[3], H2B[3] };
            uint32_t a2[4] = { H2[4], H2B[4], H2[5], H2B[5] };
            uint32_t a3[4] = { H2[6], H2B[6], H2[7], H2B[7] };
            MMA_F16(acc2[nt2], a0, u0.x, u0.y);
            MMA_F16(acc2[nt2], a1, u0.z, u0.w);
            MMA_F16(acc2[nt2], a2, u1.x, u1.y);
            MMA_F16(acc2[nt2], a3, u1.z, u1.w);
        }
    }

    // ---- epilogue: + b3 + residual, store ----
    {
        const int v_lo = v0 + R0 + g;
        const int v_hi = v_lo + 8;
        #pragma unroll
        for (int nt2 = 0; nt2 < 8; ++nt2) {
            int col = nt2 * 8 + 2 * q;
            float2 bv = *(const float2*)(sB3 + col);
            if (v_lo < N) {
                float2 xr = *(const float2*)(x_feat + (size_t)v_lo * 64 + col);
                float2 o;
                o.x = acc2[nt2][0] + bv.x + xr.x;
                o.y = acc2[nt2][1] + bv.y + xr.y;
                *(float2*)(out + (size_t)v_lo * 64 + col) = o;
            }
            if (v_hi < N) {
                float2 xr = *(const float2*)(x_feat + (size_t)v_hi * 64 + col);
                float2 o;
                o.x = acc2[nt2][2] + bv.x + xr.x;
                o.y = acc2[nt2][3] + bv.y + xr.y;
                *(float2*)(out + (size_t)v_hi * 64 + col) = o;
            }
        }
    }
}

// ---------------------------------------------------------------------------
extern "C" void kernel_launch(void* const* d_in, const int* in_sizes, int n_in,
                              void* d_out, int out_size) {
    const float* x_feat = (const float*)d_in[0];
    const int*   nbr    = (const int*)  d_in[1];
    const float* W1     = (const float*)d_in[2];
    const float* b1     = (const float*)d_in[3];
    const float* gamma  = (const float*)d_in[4];
    const float* beta   = (const float*)d_in[5];
    const float* W2     = (const float*)d_in[6];
    const float* b2     = (const float*)d_in[7];
    const float* W3     = (const float*)d_in[8];
    const float* b3     = (const float*)d_in[9];
    float* out = (float*)d_out;

    int N = in_sizes[0] / C;
    int tiles = (N + TILE_M - 1) / TILE_M;

    static int smem_set = 0;
    if (!smem_set) {
        cudaFuncSetAttribute(mlp_f16_kernel, cudaFuncAttributeMaxDynamicSharedMemorySize, SMEM_SZ);
        smem_set = 1;
    }

    int prep_elems = (N + 1) * 8 + KTAPS * 8 + 2048 + 2048;
    prep_kernel<<<(prep_elems + 255) / 256, 256>>>(x_feat, W1, W2, W3, N);

    int blocks1 = (N + DW_WARPS - 1) / DW_WARPS;
    dwconv_gn_kernel<<<blocks1, 256>>>(nbr, b1, gamma, beta, N);

    mlp_f16_kernel<<<tiles, 256, SMEM_SZ>>>(x_feat, b2, b3, out, N);
}